// round 15
// baseline (speedup 1.0000x reference)
#include <cuda_runtime.h>
#include <cuda_bf16.h>
#include <math.h>
#include <stdint.h>

#define NDIR 49
#define KDIM 147
#define KP 160            // K padded to 5 x 32 chunks
#define NPATCH 65536      // 64 * 32 * 32
#define EOUT 384
#define HW 224
#define MT 128
#define NT 64
#define NMT (NPATCH / MT) // 512
#define NNT (EOUT / NT)   // 6
#define KCH 32
#define NCHUNK (KP / KCH) // 5
#define NPART 2           // pipeline stages

// SMEM per buffer (bytes) for GEMM
#define AS_STRIDE 80
#define AS_PLANE  (128 * AS_STRIDE)   // 10240
#define BS_STRIDE 144                 // 64 n * 2B + 16B pad
#define BS_PLANE  (KCH * BS_STRIDE)   // 4608
#define OFF_AH 0
#define OFF_AL AS_PLANE
#define OFF_BH (2 * AS_PLANE)
#define OFF_BL (2 * AS_PLANE + BS_PLANE)
#define BUFSZ  (2 * AS_PLANE + 2 * BS_PLANE)  // 29696
#define SMEM_TOTAL (2 * BUFSZ)                 // 59392

// ---- scratch ----
__device__ __align__(16) __nv_bfloat16 g_Sh[(size_t)NPATCH * KP];
__device__ __align__(16) __nv_bfloat16 g_Sl[(size_t)NPATCH * KP];
__device__ __align__(16) __nv_bfloat16 g_Bh[KP * EOUT];  // [k][e]
__device__ __align__(16) __nv_bfloat16 g_Bl[KP * EOUT];
__device__ float g_u0[NDIR], g_u1[NDIR], g_sv[NDIR];

__device__ __forceinline__ float sigf(float v) { return 1.0f / (1.0f + expf(-v)); }

__device__ __forceinline__ uint32_t smem_u32(const void* p) {
    uint32_t a;
    asm("{ .reg .u64 t; cvta.to.shared.u64 t, %1; cvt.u32.u64 %0, t; }" : "=r"(a) : "l"(p));
    return a;
}

__device__ __forceinline__ void cp16(uint32_t dst, const void* src) {
    asm volatile("cp.async.cg.shared.global [%0], [%1], 16;" :: "r"(dst), "l"(src));
}

#define LDSM_X4(r, addr) \
    asm volatile("ldmatrix.sync.aligned.m8n8.x4.shared.b16 {%0,%1,%2,%3}, [%4];" \
        : "=r"((r)[0]), "=r"((r)[1]), "=r"((r)[2]), "=r"((r)[3]) : "r"(addr))

#define LDSM_X4_T(r, addr) \
    asm volatile("ldmatrix.sync.aligned.m8n8.x4.trans.shared.b16 {%0,%1,%2,%3}, [%4];" \
        : "=r"((r)[0]), "=r"((r)[1]), "=r"((r)[2]), "=r"((r)[3]) : "r"(addr))

#define MMA_BF16(d, a, b0, b1) \
    asm volatile("mma.sync.aligned.m16n8k16.row.col.f32.bf16.bf16.f32 " \
        "{%0,%1,%2,%3}, {%4,%5,%6,%7}, {%8,%9}, {%0,%1,%2,%3};" \
        : "+f"((d)[0]), "+f"((d)[1]), "+f"((d)[2]), "+f"((d)[3]) \
        : "r"((a)[0]), "r"((a)[1]), "r"((a)[2]), "r"((a)[3]), "r"(b0), "r"(b1))

__device__ __forceinline__ void split_bf(float v, __nv_bfloat16& h, __nv_bfloat16& l) {
    h = __float2bfloat16_rn(v);
    l = __float2bfloat16_rn(v - __bfloat162float(h));
}

// ---------------- init: direction table ----------------
__global__ void init_dirs_kernel() {
    int n = threadIdx.x;
    if (n >= NDIR) return;
    float u0, u1, sv;
    if (n == 0) { u0 = 1.f; u1 = 0.f; sv = 0.f; }
    else {
        int k, nk, m;
        if (n < 9)       { k = 1; nk = 8;  m = n - 1;  }
        else if (n < 25) { k = 2; nk = 16; m = n - 9;  }
        else             { k = 3; nk = 24; m = n - 25; }
        double th = 2.0 * 3.14159265358979323846 * (double)m / (double)nk;
        u0 = (float)cos(th); u1 = (float)sin(th);
        sv = (float)((double)k / 3.0);
    }
    g_u0[n] = u0; g_u1[n] = u1; g_sv[n] = sv;
}

// -------- prep: proj_w -> transposed, padded, hi/lo bf16 [k][e] --------
__global__ void bfill_kernel(const float* __restrict__ pw) {
    int idx = blockIdx.x * blockDim.x + threadIdx.x;
    if (idx >= KP * EOUT) return;
    int k = idx / EOUT, e = idx % EOUT;
    float v = (k < KDIM) ? pw[e * KDIM + k] : 0.0f;
    __nv_bfloat16 h, l;
    split_bf(v, h, l);
    g_Bh[idx] = h;
    g_Bl[idx] = l;
}

// ---------------- stage A: params + sampling (branch-free gathers) --------
__global__ __launch_bounds__(256) void sample_kernel(
    const float* __restrict__ x, const float* __restrict__ mw,
    const float* __restrict__ mb, int p_base)
{
    __shared__ float s_w[7 * KDIM];
    __shared__ float s_px[8][KDIM + 1];
    __shared__ float s_d[8][8];
    __shared__ float s_cy[8][NDIR];
    __shared__ float s_cx[8][NDIR];
    __shared__ __align__(16) __nv_bfloat16 st_h[8][KP];
    __shared__ __align__(16) __nv_bfloat16 st_l[8][KP];

    int t = threadIdx.x;
    for (int i = t; i < 7 * KDIM; i += 256) s_w[i] = mw[i];

    int warp = t >> 5, lane = t & 31;
    int p = p_base + blockIdx.x * 8 + warp;
    int b = p >> 10;
    int rem = p & 1023;
    int hp = rem >> 5, wp = rem & 31;
    const float* xb = x + (size_t)b * 3 * HW * HW;

    if (lane < KP - KDIM) {
        st_h[warp][KDIM + lane] = __float2bfloat16(0.0f);
        st_l[warp][KDIM + lane] = __float2bfloat16(0.0f);
    }

    for (int idx = lane; idx < KDIM; idx += 32) {
        int c = idx / 49, r2 = idx % 49, i = r2 / 7, j = r2 % 7;
        s_px[warp][idx] = __ldg(xb + ((size_t)c * HW + hp * 7 + i) * HW + wp * 7 + j);
    }
    __syncthreads();

    float acc[7] = {0.f,0.f,0.f,0.f,0.f,0.f,0.f};
    for (int idx = lane; idx < KDIM; idx += 32) {
        float v = s_px[warp][idx];
        #pragma unroll
        for (int f = 0; f < 7; f++) acc[f] += v * s_w[f * KDIM + idx];
    }
    #pragma unroll
    for (int f = 0; f < 7; f++) {
        #pragma unroll
        for (int off = 16; off > 0; off >>= 1)
            acc[f] += __shfl_down_sync(0xffffffffu, acc[f], off);
    }

    if (lane == 0) {
        float q0 = acc[0] + __ldg(mb + 0);
        float q1 = acc[1] + __ldg(mb + 1);
        float q2 = acc[2] + __ldg(mb + 2);
        float q3 = acc[3] + __ldg(mb + 3);
        float q4 = acc[4] + __ldg(mb + 4);
        float q5 = acc[5] + __ldg(mb + 5);
        float q6 = acc[6] + __ldg(mb + 6);
        float nrm = fmaxf(sqrtf(q0*q0 + q1*q1), 1e-12f);
        float v0 = q0 / nrm, v1 = q1 / nrm;
        float sc = 0.5f + 1.5f * sigf(q4);
        float e0 = 2.0f * sigf(q2) * sc;
        float e1 = 2.0f * sigf(q3) * sc;
        s_d[warp][0] = e0 * v0 * v0 + e1 * v1 * v1;
        s_d[warp][1] = (e0 - e1) * v0 * v1;
        s_d[warp][2] = e0 * v1 * v1 + e1 * v0 * v0;
        float wn = sqrtf(q5*q5 + q6*q6);
        float ws = 0.5f * sigf(wn);
        s_d[warp][3] = q5 * ws; s_d[warp][4] = q6 * ws;
    }
    __syncwarp();

    float m00 = s_d[warp][0], m01 = s_d[warp][1], m11 = s_d[warp][2];
    float w0 = s_d[warp][3], w1 = s_d[warp][4];
    float cy = (float)(hp * 7 + 3);
    float cx = (float)(wp * 7 + 3);
    size_t rbase = (size_t)p * KP;

    #pragma unroll
    for (int r2 = 0; r2 < 2; r2++) {
        int n = r2 * 32 + lane;
        if (n < NDIR) {
            float u0 = g_u0[n], u1 = g_u1[n], sv = g_sv[n];
            float quad = u0*u0*m00 + 2.0f*u0*u1*m01 + u1*u1*m11;
            float F = sqrtf(quad + 1e-6f) + w0 * u0 + w1 * u1;
            float tt = sv / (F + 1e-6f);
            s_cy[warp][n] = u1 * tt + cy;
            s_cx[warp][n] = u0 * tt + cx;
        }
    }
    __syncwarp();

    #pragma unroll
    for (int t5 = 0; t5 < 5; t5++) {
        int task = t5 * 32 + lane;
        if (task < KDIM) {
            int c = task / 49, n = task - c * 49;
            float py = s_cy[warp][n];
            float px = s_cx[warp][n];
            float y0 = floorf(py), x0 = floorf(px);
            float wy = py - y0, wx = px - x0;

            float wy0 = (y0 >=  0.0f && y0 <= 223.0f) ? (1.0f - wy) : 0.0f;
            float wy1 = (y0 >= -1.0f && y0 <= 222.0f) ? wy          : 0.0f;
            float wx0 = (x0 >=  0.0f && x0 <= 223.0f) ? (1.0f - wx) : 0.0f;
            float wx1 = (x0 >= -1.0f && x0 <= 222.0f) ? wx          : 0.0f;

            int iy0 = (int)fminf(fmaxf(y0,        0.0f), 223.0f);
            int iy1 = (int)fminf(fmaxf(y0 + 1.0f, 0.0f), 223.0f);
            int ix0 = (int)fminf(fmaxf(x0,        0.0f), 223.0f);
            int ix1 = (int)fminf(fmaxf(x0 + 1.0f, 0.0f), 223.0f);

            const float* xc = xb + (size_t)c * HW * HW;
            const float* r0 = xc + iy0 * HW;
            const float* r1 = xc + iy1 * HW;
            float v00 = __ldg(r0 + ix0);
            float v01 = __ldg(r0 + ix1);
            float v10 = __ldg(r1 + ix0);
            float v11 = __ldg(r1 + ix1);

            float s = wy0 * (wx0 * v00 + wx1 * v01) +
                      wy1 * (wx0 * v10 + wx1 * v11);

            __nv_bfloat16 h, l;
            split_bf(s, h, l);
            st_h[warp][task] = h;
            st_l[warp][task] = l;
        }
    }
    __syncwarp();

    if (lane < 20) {
        ((uint4*)(g_Sh + rbase))[lane] = ((const uint4*)st_h[warp])[lane];
        ((uint4*)(g_Sl + rbase))[lane] = ((const uint4*)st_l[warp])[lane];
    }
}

// ---------------- stage B: bf16 mma.sync GEMM (2 CTAs/SM for co-residency) -
__global__ void __launch_bounds__(256, 2)
gemm_mma(const float* __restrict__ pb, float* __restrict__ out, int m_base)
{
    extern __shared__ __align__(16) char smem[];
    uint32_t sb = smem_u32(smem);
    int tid = threadIdx.x, wid = tid >> 5, lane = tid & 31;
    int warp_m = wid & 3, warp_n = wid >> 2;
    int bm = (blockIdx.y + m_base) * MT;
    int bn = blockIdx.x * NT;

    auto issue_chunk = [&](int ch, int buf) {
        uint32_t bb = sb + buf * BUFSZ;
        #pragma unroll
        for (int i = 0; i < 2; i++) {
            int idx = i * 256 + tid;
            int r = idx >> 2, seg = idx & 3;
            size_t goff = (size_t)(bm + r) * KP + ch * KCH + seg * 8;
            cp16(bb + OFF_AH + r * AS_STRIDE + seg * 16, g_Sh + goff);
            cp16(bb + OFF_AL + r * AS_STRIDE + seg * 16, g_Sl + goff);
        }
        {
            int r = tid >> 3, seg = tid & 7;
            size_t goff = (size_t)(ch * KCH + r) * EOUT + bn + seg * 8;
            cp16(bb + OFF_BH + r * BS_STRIDE + seg * 16, g_Bh + goff);
            cp16(bb + OFF_BL + r * BS_STRIDE + seg * 16, g_Bl + goff);
        }
        asm volatile("cp.async.commit_group;" ::: "memory");
    };

    float acc[2][4][4];
    #pragma unroll
    for (int i = 0; i < 2; i++)
        #pragma unroll
        for (int j = 0; j < 4; j++)
            #pragma unroll
            for (int q = 0; q < 4; q++) acc[i][j][q] = 0.0f;

    issue_chunk(0, 0);

    uint32_t a_off = (uint32_t)((warp_m * 32 + (lane & 15)) * AS_STRIDE + (lane >> 4) * 16);
    uint32_t b_off = (uint32_t)(OFF_BH + ((lane & 7) + ((lane >> 3) & 1) * 8) * BS_STRIDE +
                                (warp_n * 32 + (lane >> 4) * 8) * 2);

    #pragma unroll 1
    for (int ch = 0; ch < NCHUNK; ch++) {
        int buf = ch & 1;
        asm volatile("cp.async.wait_group 0;" ::: "memory");
        __syncthreads();
        if (ch + 1 < NCHUNK) issue_chunk(ch + 1, 1 - buf);

        uint32_t bb = sb + buf * BUFSZ;
        #pragma unroll
        for (int ks = 0; ks < 2; ks++) {
            uint32_t ah[2][4], al[2][4];
            #pragma unroll
            for (int mt = 0; mt < 2; mt++) {
                uint32_t aaddr = bb + a_off + mt * 16 * AS_STRIDE + ks * 32;
                LDSM_X4(ah[mt], aaddr);
                LDSM_X4(al[mt], aaddr + AS_PLANE);
            }
            #pragma unroll
            for (int np = 0; np < 2; np++) {
                uint32_t baddr = bb + b_off + ks * 16 * BS_STRIDE + np * 32;
                uint32_t bh[4], bl[4];
                LDSM_X4_T(bh, baddr);
                LDSM_X4_T(bl, baddr + BS_PLANE);
                #pragma unroll
                for (int mt = 0; mt < 2; mt++) {
                    #pragma unroll
                    for (int j = 0; j < 2; j++) {
                        float* d = acc[mt][np * 2 + j];
                        MMA_BF16(d, ah[mt], bh[j * 2], bh[j * 2 + 1]);
                        MMA_BF16(d, al[mt], bh[j * 2], bh[j * 2 + 1]);
                        MMA_BF16(d, ah[mt], bl[j * 2], bl[j * 2 + 1]);
                    }
                }
            }
        }
    }

    // epilogue
    #pragma unroll
    for (int mt = 0; mt < 2; mt++) {
        int row0 = bm + warp_m * 32 + mt * 16 + (lane >> 2);
        #pragma unroll
        for (int nt = 0; nt < 4; nt++) {
            int cloc = warp_n * 32 + nt * 8 + (lane & 3) * 2;
            float b0 = __ldg(pb + bn + cloc);
            float b1 = __ldg(pb + bn + cloc + 1);
            float* o0 = out + (size_t)row0 * EOUT + bn + cloc;
            float* o1 = o0 + 8 * EOUT;
            float2 v0 = {acc[mt][nt][0] + b0, acc[mt][nt][1] + b1};
            float2 v1 = {acc[mt][nt][2] + b0, acc[mt][nt][3] + b1};
            *(float2*)o0 = v0;
            *(float2*)o1 = v1;
        }
    }
}

extern "C" void kernel_launch(void* const* d_in, const int* in_sizes, int n_in,
                              void* d_out, int out_size)
{
    const float* x  = (const float*)d_in[0];
    const float* mw = (const float*)d_in[1];
    const float* mb = (const float*)d_in[2];
    const float* pw = (const float*)d_in[3];
    const float* pb = (const float*)d_in[4];
    float* out = (float*)d_out;

    static bool inited = false;
    static cudaStream_t sA, sB;
    static cudaEvent_t e0, eS[NPART], eB;
    if (!inited) {
        cudaStreamCreateWithFlags(&sA, cudaStreamNonBlocking);
        cudaStreamCreateWithFlags(&sB, cudaStreamNonBlocking);
        cudaEventCreateWithFlags(&e0, cudaEventDisableTiming);
        for (int i = 0; i < NPART; i++)
            cudaEventCreateWithFlags(&eS[i], cudaEventDisableTiming);
        cudaEventCreateWithFlags(&eB, cudaEventDisableTiming);
        cudaFuncSetAttribute(gemm_mma, cudaFuncAttributeMaxDynamicSharedMemorySize, SMEM_TOTAL);
        inited = true;
    }

    // fork both worker streams off the (capturing) default stream
    cudaEventRecord(e0, 0);
    cudaStreamWaitEvent(sA, e0, 0);
    cudaStreamWaitEvent(sB, e0, 0);

    init_dirs_kernel<<<1, 64, 0, sA>>>();
    bfill_kernel<<<(KP * EOUT + 255) / 256, 256, 0, sB>>>(pw);

    const int SBLK = (NPATCH / 8) / NPART;   // 4096 sampler blocks per part
    const int GTM  = NMT / NPART;            // 256 m-tiles per part
    for (int i = 0; i < NPART; i++) {
        sample_kernel<<<SBLK, 256, 0, sA>>>(x, mw, mb, i * SBLK * 8);
        cudaEventRecord(eS[i], sA);
        cudaStreamWaitEvent(sB, eS[i], 0);
        gemm_mma<<<dim3(NNT, GTM), 256, SMEM_TOTAL, sB>>>(pb, out, i * GTM);
    }

    // join back to default stream
    cudaEventRecord(eB, sB);
    cudaStreamWaitEvent(0, eB, 0);
}

// round 16
// speedup vs baseline: 1.0944x; 1.0944x over previous
#include <cuda_runtime.h>
#include <cuda_bf16.h>
#include <math.h>
#include <stdint.h>

#define NDIR 49
#define KDIM 147
#define KP 160            // K padded to 5 x 32 chunks
#define NPATCH 65536      // 64 * 32 * 32
#define EOUT 384
#define HW 224
#define MT 128
#define NT 64
#define NMT (NPATCH / MT) // 512
#define NNT (EOUT / NT)   // 6
#define KCH 32
#define NCHUNK (KP / KCH) // 5

// SMEM per buffer (bytes) for GEMM
#define AS_STRIDE 80
#define AS_PLANE  (128 * AS_STRIDE)   // 10240
#define BS_STRIDE 144                 // 64 n * 2B + 16B pad
#define BS_PLANE  (KCH * BS_STRIDE)   // 4608
#define OFF_AH 0
#define OFF_AL AS_PLANE
#define OFF_BH (2 * AS_PLANE)
#define OFF_BL (2 * AS_PLANE + BS_PLANE)
#define BUFSZ  (2 * AS_PLANE + 2 * BS_PLANE)  // 29696
#define SMEM_TOTAL (2 * BUFSZ)                 // 59392

// ---- scratch ----
__device__ __align__(16) __nv_bfloat16 g_Sh[(size_t)NPATCH * KP];
__device__ __align__(16) __nv_bfloat16 g_Sl[(size_t)NPATCH * KP];
__device__ __align__(16) __nv_bfloat16 g_Bh[KP * EOUT];  // [k][e]
__device__ __align__(16) __nv_bfloat16 g_Bl[KP * EOUT];
__device__ __align__(16) float g_Prm[(size_t)NPATCH * 8];  // m00,m01,m11,w0,w1
__device__ float g_u0[NDIR], g_u1[NDIR], g_sv[NDIR];

__device__ __forceinline__ float sigf(float v) { return 1.0f / (1.0f + expf(-v)); }

__device__ __forceinline__ uint32_t smem_u32(const void* p) {
    uint32_t a;
    asm("{ .reg .u64 t; cvta.to.shared.u64 t, %1; cvt.u32.u64 %0, t; }" : "=r"(a) : "l"(p));
    return a;
}

__device__ __forceinline__ void cp16(uint32_t dst, const void* src) {
    asm volatile("cp.async.cg.shared.global [%0], [%1], 16;" :: "r"(dst), "l"(src));
}

#define LDSM_X4(r, addr) \
    asm volatile("ldmatrix.sync.aligned.m8n8.x4.shared.b16 {%0,%1,%2,%3}, [%4];" \
        : "=r"((r)[0]), "=r"((r)[1]), "=r"((r)[2]), "=r"((r)[3]) : "r"(addr))

#define LDSM_X4_T(r, addr) \
    asm volatile("ldmatrix.sync.aligned.m8n8.x4.trans.shared.b16 {%0,%1,%2,%3}, [%4];" \
        : "=r"((r)[0]), "=r"((r)[1]), "=r"((r)[2]), "=r"((r)[3]) : "r"(addr))

#define MMA_BF16(d, a, b0, b1) \
    asm volatile("mma.sync.aligned.m16n8k16.row.col.f32.bf16.bf16.f32 " \
        "{%0,%1,%2,%3}, {%4,%5,%6,%7}, {%8,%9}, {%0,%1,%2,%3};" \
        : "+f"((d)[0]), "+f"((d)[1]), "+f"((d)[2]), "+f"((d)[3]) \
        : "r"((a)[0]), "r"((a)[1]), "r"((a)[2]), "r"((a)[3]), "r"(b0), "r"(b1))

__device__ __forceinline__ void split_bf(float v, __nv_bfloat16& h, __nv_bfloat16& l) {
    h = __float2bfloat16_rn(v);
    l = __float2bfloat16_rn(v - __bfloat162float(h));
}

// ---------------- init: direction table ----------------
__global__ void init_dirs_kernel() {
    int n = threadIdx.x;
    if (n >= NDIR) return;
    float u0, u1, sv;
    if (n == 0) { u0 = 1.f; u1 = 0.f; sv = 0.f; }
    else {
        int k, nk, m;
        if (n < 9)       { k = 1; nk = 8;  m = n - 1;  }
        else if (n < 25) { k = 2; nk = 16; m = n - 9;  }
        else             { k = 3; nk = 24; m = n - 25; }
        double th = 2.0 * 3.14159265358979323846 * (double)m / (double)nk;
        u0 = (float)cos(th); u1 = (float)sin(th);
        sv = (float)((double)k / 3.0);
    }
    g_u0[n] = u0; g_u1[n] = u1; g_sv[n] = sv;
}

// -------- prep: proj_w -> transposed, padded, hi/lo bf16 [k][e] --------
__global__ void bfill_kernel(const float* __restrict__ pw) {
    int idx = blockIdx.x * blockDim.x + threadIdx.x;
    if (idx >= KP * EOUT) return;
    int k = idx / EOUT, e = idx % EOUT;
    float v = (k < KDIM) ? pw[e * KDIM + k] : 0.0f;
    __nv_bfloat16 h, l;
    split_bf(v, h, l);
    g_Bh[idx] = h;
    g_Bl[idx] = l;
}

// ---------------- stage A1: per-patch conv params ----------------
__global__ __launch_bounds__(256) void params_kernel(
    const float* __restrict__ x, const float* __restrict__ mw, const float* __restrict__ mb)
{
    __shared__ float s_w[7 * KDIM];
    int t = threadIdx.x;
    for (int i = t; i < 7 * KDIM; i += 256) s_w[i] = mw[i];
    __syncthreads();

    int warp = t >> 5, lane = t & 31;
    int p = blockIdx.x * 8 + warp;
    int b = p >> 10;
    int rem = p & 1023;
    int hp = rem >> 5, wp = rem & 31;
    const float* xb = x + (size_t)b * 3 * HW * HW;

    float acc[7] = {0.f,0.f,0.f,0.f,0.f,0.f,0.f};
    for (int idx = lane; idx < KDIM; idx += 32) {
        int c = idx / 49, r2 = idx % 49, i = r2 / 7, j = r2 % 7;
        float v = __ldg(xb + ((size_t)c * HW + hp * 7 + i) * HW + wp * 7 + j);
        #pragma unroll
        for (int f = 0; f < 7; f++) acc[f] += v * s_w[f * KDIM + idx];
    }
    #pragma unroll
    for (int f = 0; f < 7; f++) {
        #pragma unroll
        for (int off = 16; off > 0; off >>= 1)
            acc[f] += __shfl_down_sync(0xffffffffu, acc[f], off);
    }

    if (lane == 0) {
        float q0 = acc[0] + __ldg(mb + 0);
        float q1 = acc[1] + __ldg(mb + 1);
        float q2 = acc[2] + __ldg(mb + 2);
        float q3 = acc[3] + __ldg(mb + 3);
        float q4 = acc[4] + __ldg(mb + 4);
        float q5 = acc[5] + __ldg(mb + 5);
        float q6 = acc[6] + __ldg(mb + 6);
        float nrm = fmaxf(sqrtf(q0*q0 + q1*q1), 1e-12f);
        float v0 = q0 / nrm, v1 = q1 / nrm;
        float sc = 0.5f + 1.5f * sigf(q4);
        float e0 = 2.0f * sigf(q2) * sc;
        float e1 = 2.0f * sigf(q3) * sc;
        float wn = sqrtf(q5*q5 + q6*q6);
        float ws = 0.5f * sigf(wn);
        float* dst = g_Prm + (size_t)p * 8;
        dst[0] = e0 * v0 * v0 + e1 * v1 * v1;
        dst[1] = (e0 - e1) * v0 * v1;
        dst[2] = e0 * v1 * v1 + e1 * v0 * v0;
        dst[3] = q5 * ws;
        dst[4] = q6 * ws;
    }
}

// ---------------- stage A2: gathers (lean, high-occupancy) ----------------
__global__ __launch_bounds__(256, 4) void gather_kernel(const float* __restrict__ x)
{
    __shared__ float s_cy[8][NDIR];
    __shared__ float s_cx[8][NDIR];
    __shared__ __align__(16) __nv_bfloat16 st_h[8][KP];
    __shared__ __align__(16) __nv_bfloat16 st_l[8][KP];

    int t = threadIdx.x;
    int warp = t >> 5, lane = t & 31;
    int p = blockIdx.x * 8 + warp;
    int b = p >> 10;
    int rem = p & 1023;
    int hp = rem >> 5, wp = rem & 31;
    const float* xb = x + (size_t)b * 3 * HW * HW;

    // params broadcast: lanes read 8 consecutive floats, shfl from lanes 0-4
    float prm = __ldg(g_Prm + (size_t)p * 8 + (lane & 7));
    float m00 = __shfl_sync(0xffffffffu, prm, 0);
    float m01 = __shfl_sync(0xffffffffu, prm, 1);
    float m11 = __shfl_sync(0xffffffffu, prm, 2);
    float w0  = __shfl_sync(0xffffffffu, prm, 3);
    float w1  = __shfl_sync(0xffffffffu, prm, 4);

    if (lane < KP - KDIM) {
        st_h[warp][KDIM + lane] = __float2bfloat16(0.0f);
        st_l[warp][KDIM + lane] = __float2bfloat16(0.0f);
    }

    float cy = (float)(hp * 7 + 3);
    float cx = (float)(wp * 7 + 3);
    size_t rbase = (size_t)p * KP;

    #pragma unroll
    for (int r2 = 0; r2 < 2; r2++) {
        int n = r2 * 32 + lane;
        if (n < NDIR) {
            float u0 = g_u0[n], u1 = g_u1[n], sv = g_sv[n];
            float quad = u0*u0*m00 + 2.0f*u0*u1*m01 + u1*u1*m11;
            float F = sqrtf(quad + 1e-6f) + w0 * u0 + w1 * u1;
            float tt = sv / (F + 1e-6f);
            s_cy[warp][n] = u1 * tt + cy;
            s_cx[warp][n] = u0 * tt + cx;
        }
    }
    __syncwarp();

    // branch-free clamped gathers
    #pragma unroll
    for (int t5 = 0; t5 < 5; t5++) {
        int task = t5 * 32 + lane;
        if (task < KDIM) {
            int c = task / 49, n = task - c * 49;
            float py = s_cy[warp][n];
            float px = s_cx[warp][n];
            float y0 = floorf(py), x0 = floorf(px);
            float wy = py - y0, wx = px - x0;

            float wy0 = (y0 >=  0.0f && y0 <= 223.0f) ? (1.0f - wy) : 0.0f;
            float wy1 = (y0 >= -1.0f && y0 <= 222.0f) ? wy          : 0.0f;
            float wx0 = (x0 >=  0.0f && x0 <= 223.0f) ? (1.0f - wx) : 0.0f;
            float wx1 = (x0 >= -1.0f && x0 <= 222.0f) ? wx          : 0.0f;

            int iy0 = (int)fminf(fmaxf(y0,        0.0f), 223.0f);
            int iy1 = (int)fminf(fmaxf(y0 + 1.0f, 0.0f), 223.0f);
            int ix0 = (int)fminf(fmaxf(x0,        0.0f), 223.0f);
            int ix1 = (int)fminf(fmaxf(x0 + 1.0f, 0.0f), 223.0f);

            const float* xc = xb + (size_t)c * HW * HW;
            const float* r0 = xc + iy0 * HW;
            const float* r1 = xc + iy1 * HW;
            float v00 = __ldg(r0 + ix0);
            float v01 = __ldg(r0 + ix1);
            float v10 = __ldg(r1 + ix0);
            float v11 = __ldg(r1 + ix1);

            float s = wy0 * (wx0 * v00 + wx1 * v01) +
                      wy1 * (wx0 * v10 + wx1 * v11);

            __nv_bfloat16 h, l;
            split_bf(s, h, l);
            st_h[warp][task] = h;
            st_l[warp][task] = l;
        }
    }
    __syncwarp();

    if (lane < 20) {
        ((uint4*)(g_Sh + rbase))[lane] = ((const uint4*)st_h[warp])[lane];
        ((uint4*)(g_Sl + rbase))[lane] = ((const uint4*)st_l[warp])[lane];
    }
}

// ---------------- stage B: bf16 mma.sync 3-product GEMM (R9 best) ---------
__global__ void __launch_bounds__(256, 3)
gemm_mma(const float* __restrict__ pb, float* __restrict__ out)
{
    extern __shared__ __align__(16) char smem[];
    uint32_t sb = smem_u32(smem);
    int tid = threadIdx.x, wid = tid >> 5, lane = tid & 31;
    int warp_m = wid & 3, warp_n = wid >> 2;
    int bm = blockIdx.y * MT;
    int bn = blockIdx.x * NT;

    auto issue_chunk = [&](int ch, int buf) {
        uint32_t bb = sb + buf * BUFSZ;
        #pragma unroll
        for (int i = 0; i < 2; i++) {
            int idx = i * 256 + tid;
            int r = idx >> 2, seg = idx & 3;
            size_t goff = (size_t)(bm + r) * KP + ch * KCH + seg * 8;
            cp16(bb + OFF_AH + r * AS_STRIDE + seg * 16, g_Sh + goff);
            cp16(bb + OFF_AL + r * AS_STRIDE + seg * 16, g_Sl + goff);
        }
        {
            int r = tid >> 3, seg = tid & 7;
            size_t goff = (size_t)(ch * KCH + r) * EOUT + bn + seg * 8;
            cp16(bb + OFF_BH + r * BS_STRIDE + seg * 16, g_Bh + goff);
            cp16(bb + OFF_BL + r * BS_STRIDE + seg * 16, g_Bl + goff);
        }
        asm volatile("cp.async.commit_group;" ::: "memory");
    };

    float acc[2][4][4];
    #pragma unroll
    for (int i = 0; i < 2; i++)
        #pragma unroll
        for (int j = 0; j < 4; j++)
            #pragma unroll
            for (int q = 0; q < 4; q++) acc[i][j][q] = 0.0f;

    issue_chunk(0, 0);

    uint32_t a_off = (uint32_t)((warp_m * 32 + (lane & 15)) * AS_STRIDE + (lane >> 4) * 16);
    uint32_t b_off = (uint32_t)(OFF_BH + ((lane & 7) + ((lane >> 3) & 1) * 8) * BS_STRIDE +
                                (warp_n * 32 + (lane >> 4) * 8) * 2);

    #pragma unroll 1
    for (int ch = 0; ch < NCHUNK; ch++) {
        int buf = ch & 1;
        asm volatile("cp.async.wait_group 0;" ::: "memory");
        __syncthreads();
        if (ch + 1 < NCHUNK) issue_chunk(ch + 1, 1 - buf);

        uint32_t bb = sb + buf * BUFSZ;
        #pragma unroll
        for (int ks = 0; ks < 2; ks++) {
            uint32_t ah[2][4], al[2][4];
            #pragma unroll
            for (int mt = 0; mt < 2; mt++) {
                uint32_t aaddr = bb + a_off + mt * 16 * AS_STRIDE + ks * 32;
                LDSM_X4(ah[mt], aaddr);
                LDSM_X4(al[mt], aaddr + AS_PLANE);
            }
            #pragma unroll
            for (int np = 0; np < 2; np++) {
                uint32_t baddr = bb + b_off + ks * 16 * BS_STRIDE + np * 32;
                uint32_t bh[4], bl[4];
                LDSM_X4_T(bh, baddr);
                LDSM_X4_T(bl, baddr + BS_PLANE);
                #pragma unroll
                for (int mt = 0; mt < 2; mt++) {
                    #pragma unroll
                    for (int j = 0; j < 2; j++) {
                        float* d = acc[mt][np * 2 + j];
                        MMA_BF16(d, ah[mt], bh[j * 2], bh[j * 2 + 1]);
                        MMA_BF16(d, al[mt], bh[j * 2], bh[j * 2 + 1]);
                        MMA_BF16(d, ah[mt], bl[j * 2], bl[j * 2 + 1]);
                    }
                }
            }
        }
    }

    // epilogue
    #pragma unroll
    for (int mt = 0; mt < 2; mt++) {
        int row0 = bm + warp_m * 32 + mt * 16 + (lane >> 2);
        #pragma unroll
        for (int nt = 0; nt < 4; nt++) {
            int cloc = warp_n * 32 + nt * 8 + (lane & 3) * 2;
            float b0 = __ldg(pb + bn + cloc);
            float b1 = __ldg(pb + bn + cloc + 1);
            float* o0 = out + (size_t)row0 * EOUT + bn + cloc;
            float* o1 = o0 + 8 * EOUT;
            float2 v0 = {acc[mt][nt][0] + b0, acc[mt][nt][1] + b1};
            float2 v1 = {acc[mt][nt][2] + b0, acc[mt][nt][3] + b1};
            *(float2*)o0 = v0;
            *(float2*)o1 = v1;
        }
    }
}

extern "C" void kernel_launch(void* const* d_in, const int* in_sizes, int n_in,
                              void* d_out, int out_size)
{
    const float* x  = (const float*)d_in[0];
    const float* mw = (const float*)d_in[1];
    const float* mb = (const float*)d_in[2];
    const float* pw = (const float*)d_in[3];
    const float* pb = (const float*)d_in[4];
    float* out = (float*)d_out;

    cudaFuncSetAttribute(gemm_mma, cudaFuncAttributeMaxDynamicSharedMemorySize, SMEM_TOTAL);

    init_dirs_kernel<<<1, 64>>>();
    bfill_kernel<<<(KP * EOUT + 255) / 256, 256>>>(pw);
    params_kernel<<<NPATCH / 8, 256>>>(x, mw, mb);
    gather_kernel<<<NPATCH / 8, 256>>>(x);
    gemm_mma<<<dim3(NNT, NMT), 256, SMEM_TOTAL>>>(pb, out);
}